// round 14
// baseline (speedup 1.0000x reference)
#include <cuda_runtime.h>
#include <cuda_bf16.h>
#include <math.h>
#include <stdint.h>

#define NN 50000
#define NH 10000
#define NE 250000
#define DIM 512
#define NSLOT 24

// ---------------------------------------------------------------------------
// Static scratch (no allocation allowed)
// ---------------------------------------------------------------------------
__device__ float g_n0[(size_t)NN * DIM];
__device__ float g_n1[(size_t)NN * DIM];
__device__ float g_n2[(size_t)NN * DIM];
__device__ float g_h0[(size_t)NH * DIM];
__device__ float g_h1[(size_t)NH * DIM];
__device__ float g_h2[(size_t)NH * DIM];
__device__ float2 g_stat[NN];
__device__ float2 g_acc[NN];      // (sum, sumsq) accumulator; zero-invariant
__device__ int   g_minv;
// packed split weights: [slot][kpair][n], word = bf16(k even)|bf16(k odd)<<16
__device__ uint32_t g_wph[(size_t)NSLOT * 256 * 512];
__device__ uint32_t g_wpl[(size_t)NSLOT * 256 * 512];
// CSR structures (rebuilt every call)
__device__ int g_cntE[NH], g_cntV[NN];
__device__ int g_curE[NH], g_curV[NN];
__device__ int g_rpE[NH + 1], g_rpV[NN + 1];
__device__ int g_colE[NE], g_colV[NE];

// ---------------------------------------------------------------------------
// Graph preprocessing
// ---------------------------------------------------------------------------
__global__ void k_init_min() { g_minv = 0x7fffffff; }

__global__ void k_min_reduce(const int* __restrict__ idx, int n) {
    int v = 0x7fffffff;
    for (int i = blockIdx.x * blockDim.x + threadIdx.x; i < n;
         i += gridDim.x * blockDim.x)
        v = min(v, __ldg(idx + i));
#pragma unroll
    for (int o = 16; o > 0; o >>= 1) v = min(v, __shfl_xor_sync(0xffffffffu, v, o));
    if ((threadIdx.x & 31) == 0) atomicMin(&g_minv, v);
}

__global__ void k_zero4(float4* __restrict__ p, size_t n4) {
    size_t i = (size_t)blockIdx.x * blockDim.x + threadIdx.x;
    size_t stride = (size_t)gridDim.x * blockDim.x;
    float4 z = make_float4(0.f, 0.f, 0.f, 0.f);
    for (; i < n4; i += stride) p[i] = z;
}

__global__ void k_cnt(const int* __restrict__ idx, int* __restrict__ cnt,
                      int n, int shift) {
    int i = blockIdx.x * blockDim.x + threadIdx.x;
    if (i < n) atomicAdd(&cnt[__ldg(idx + i) - (shift ? g_minv : 0)], 1);
}

__global__ __launch_bounds__(1024) void k_scan(const int* __restrict__ cnt,
                                               int* __restrict__ rp, int n) {
    __shared__ int part[1024];
    int t = threadIdx.x;
    int C = (n + 1023) >> 10;
    int base = t * C;
    int sum = 0;
    for (int i = 0; i < C; i++)
        if (base + i < n) sum += cnt[base + i];
    part[t] = sum;
    __syncthreads();
    for (int o = 1; o < 1024; o <<= 1) {
        int v = (t >= o) ? part[t - o] : 0;
        __syncthreads();
        part[t] += v;
        __syncthreads();
    }
    int excl = (t == 0) ? 0 : part[t - 1];
    for (int i = 0; i < C; i++)
        if (base + i < n) { rp[base + i] = excl; excl += cnt[base + i]; }
    if (t == 1023) rp[n] = part[1023];
}

__global__ void k_fill(const int* __restrict__ idx, const int* __restrict__ rp,
                       int* __restrict__ cur, int* __restrict__ col,
                       int n, int shift) {
    int i = blockIdx.x * blockDim.x + threadIdx.x;
    if (i < n) {
        int s = __ldg(idx + i) - (shift ? g_minv : 0);
        int p = atomicAdd(&cur[s], 1);
        col[rp[s] + p] = i;
    }
}

// ---------------------------------------------------------------------------
// Weight pre-split + pack
// ---------------------------------------------------------------------------
__global__ void k_wsplit(const float* __restrict__ W, uint32_t* __restrict__ oh,
                         uint32_t* __restrict__ ol, int nmat) {
    int i = blockIdx.x * blockDim.x + threadIdx.x;
    int total = nmat * 256 * 512;
    if (i >= total) return;
    int mat = i >> 17;
    int rem = i & 131071;
    int kp = rem >> 9, n = rem & 511;
    const float* src = W + (size_t)mat * DIM * DIM;
    float a = __ldg(src + (size_t)(2 * kp) * DIM + n);
    float b = __ldg(src + (size_t)(2 * kp + 1) * DIM + n);
    __nv_bfloat16 ha = __float2bfloat16(a), hb = __float2bfloat16(b);
    oh[i] = (uint32_t)__bfloat16_as_ushort(ha) |
            ((uint32_t)__bfloat16_as_ushort(hb) << 16);
    ol[i] = (uint32_t)__bfloat16_as_ushort(__float2bfloat16(a - __bfloat162float(ha))) |
            ((uint32_t)__bfloat16_as_ushort(__float2bfloat16(b - __bfloat162float(hb))) << 16);
}

// ---------------------------------------------------------------------------
// LN row statistics from a full tensor (used ONCE for the input x)
// ---------------------------------------------------------------------------
__global__ __launch_bounds__(256) void k_stat(const float* __restrict__ in,
                                              float2* __restrict__ st, int N) {
    int warp = threadIdx.x >> 5, lane = threadIdx.x & 31;
    int row = blockIdx.x * 8 + warp;
    if (row >= N) return;
    const float4* ip = reinterpret_cast<const float4*>(in + (size_t)row * DIM);
    float s = 0.f, ss = 0.f;
#pragma unroll
    for (int j = 0; j < 4; j++) {
        float4 v = ip[lane + 32 * j];
        s  += v.x + v.y + v.z + v.w;
        ss += v.x * v.x + v.y * v.y + v.z * v.z + v.w * v.w;
    }
#pragma unroll
    for (int o = 16; o > 0; o >>= 1) {
        s  += __shfl_xor_sync(0xffffffffu, s, o);
        ss += __shfl_xor_sync(0xffffffffu, ss, o);
    }
    if (lane == 0) {
        float mu = s * (1.f / DIM);
        st[row] = make_float2(mu, rsqrtf(ss * (1.f / DIM) - mu * mu + 1e-5f));
    }
}

// Finalize accumulated (sum,sumsq) -> (mu, rstd); re-zero accumulator
__global__ void k_fin(float2* __restrict__ acc, float2* __restrict__ st, int N) {
    int i = blockIdx.x * blockDim.x + threadIdx.x;
    if (i >= N) return;
    float2 a = acc[i];
    float mu = a.x * (1.f / DIM);
    st[i] = make_float2(mu, rsqrtf(a.y * (1.f / DIM) - mu * mu + 1e-5f));
    acc[i] = make_float2(0.f, 0.f);
}

// ---------------------------------------------------------------------------
// CSR segment-mean gather; also emits LN stats of its output rows
// ---------------------------------------------------------------------------
__global__ __launch_bounds__(128) void k_gather(
    const float* __restrict__ feat, float* __restrict__ out,
    const int* __restrict__ rp, const int* __restrict__ col,
    const int* __restrict__ gidx, const float* __restrict__ norm, int gshift,
    float2* __restrict__ st)
{
    int seg = blockIdx.x;
    int beg = rp[seg], end = rp[seg + 1];
    int t = threadIdx.x;
    int mv = g_minv;
    __shared__ int   se[128];
    __shared__ float sn[128];
    __shared__ float rs[4], rss[4];
    float4 acc = make_float4(0.f, 0.f, 0.f, 0.f);
    for (int base = beg; base < end; base += 128) {
        int nb = min(128, end - base);
        if (t < nb) {
            int e = __ldg(col + base + t);
            se[t] = __ldg(gidx + e) - (gshift ? mv : 0);
            sn[t] = __ldg(norm + e);
        }
        __syncthreads();
        for (int j = 0; j < nb; j++) {
            float4 v = *reinterpret_cast<const float4*>(
                feat + (size_t)se[j] * DIM + t * 4);
            float nv = sn[j];
            acc.x = fmaf(nv, v.x, acc.x);
            acc.y = fmaf(nv, v.y, acc.y);
            acc.z = fmaf(nv, v.z, acc.z);
            acc.w = fmaf(nv, v.w, acc.w);
        }
        __syncthreads();
    }
    float inv = 1.f / fmaxf((float)(end - beg), 1.f);
    acc.x *= inv; acc.y *= inv; acc.z *= inv; acc.w *= inv;
    *reinterpret_cast<float4*>(out + (size_t)seg * DIM + t * 4) = acc;

    // LN stats of this output row
    float s  = acc.x + acc.y + acc.z + acc.w;
    float ss = acc.x * acc.x + acc.y * acc.y + acc.z * acc.z + acc.w * acc.w;
#pragma unroll
    for (int o = 16; o > 0; o >>= 1) {
        s  += __shfl_xor_sync(0xffffffffu, s, o);
        ss += __shfl_xor_sync(0xffffffffu, ss, o);
    }
    int wid = t >> 5;
    if ((t & 31) == 0) { rs[wid] = s; rss[wid] = ss; }
    __syncthreads();
    if (t == 0) {
        s  = rs[0] + rs[1] + rs[2] + rs[3];
        ss = rss[0] + rss[1] + rss[2] + rss[3];
        float mu = s * (1.f / DIM);
        st[seg] = make_float2(mu, rsqrtf(ss * (1.f / DIM) - mu * mu + 1e-5f));
    }
}

// ---------------------------------------------------------------------------
// Split-bf16 GEMM: double-buffered; packed-W via cp.async; fused LN on A;
// optional stat emission from the epilogue.
// ---------------------------------------------------------------------------
#define ASTR 36
#define BSTR 136
#define A_WORDS (128 * ASTR)
#define SSTR (A_WORDS + 32 * BSTR)
#define GEMM_SMEM (2 * SSTR * 4)

__device__ __forceinline__ uint32_t pack_hi(float a, float b, uint32_t& lo) {
    __nv_bfloat16 ha = __float2bfloat16(a), hb = __float2bfloat16(b);
    lo = (uint32_t)__bfloat16_as_ushort(__float2bfloat16(a - __bfloat162float(ha))) |
         ((uint32_t)__bfloat16_as_ushort(__float2bfloat16(b - __bfloat162float(hb))) << 16);
    return (uint32_t)__bfloat16_as_ushort(ha) |
           ((uint32_t)__bfloat16_as_ushort(hb) << 16);
}

__device__ __forceinline__ void mma_bf16(float* c, const uint32_t* a,
                                         const uint32_t* b) {
    asm volatile(
        "mma.sync.aligned.m16n8k16.row.col.f32.bf16.bf16.f32 "
        "{%0,%1,%2,%3}, {%4,%5,%6,%7}, {%8,%9}, {%0,%1,%2,%3};"
        : "+f"(c[0]), "+f"(c[1]), "+f"(c[2]), "+f"(c[3])
        : "r"(a[0]), "r"(a[1]), "r"(a[2]), "r"(a[3]), "r"(b[0]), "r"(b[1]));
}

__device__ __forceinline__ void cp16(uint32_t d, const void* s) {
    asm volatile("cp.async.cg.shared.global [%0], [%1], 16;"
                 :: "r"(d), "l"(s) : "memory");
}

__device__ __forceinline__ uint32_t s2u(const void* p) {
    uint32_t r;
    asm("{ .reg .u64 t; cvta.to.shared.u64 t, %1; cvt.u32.u64 %0, t; }"
        : "=r"(r) : "l"(p));
    return r;
}

__global__ __launch_bounds__(256, 2) void k_gemm_tc(
    const float* __restrict__ A,
    const uint32_t* __restrict__ Wh, const uint32_t* __restrict__ Wl,
    const float* __restrict__ bias, float* __restrict__ C, int M, int relu,
    const float2* __restrict__ stat, const float* __restrict__ lnw,
    const float* __restrict__ lnb, int emit, float2* __restrict__ accv)
{
    extern __shared__ uint32_t sm[];
    const uint32_t smb = s2u(sm);

    const int t    = threadIdx.x;
    const int bm   = blockIdx.y * 128;
    const int bn   = blockIdx.x * 128;
    const int w    = t >> 5;
    const int lane = t & 31;
    const int g    = lane >> 2;
    const int tig  = lane & 3;
    const int m0   = (w & 1) * 64;
    const int n0   = (w >> 1) * 32;

    const int ar = t >> 3;
    const int ak = (t & 7) << 2;
    const int ap = (t & 7) << 1;

    float acc[4][4][4];
#pragma unroll
    for (int mf = 0; mf < 4; mf++)
#pragma unroll
        for (int nf = 0; nf < 4; nf++)
#pragma unroll
            for (int i = 0; i < 4; i++) acc[mf][nf][i] = 0.f;

    uint32_t uh[4][2], ul[4][2];

    auto loadRegs = [&](int i) {
        int kk = i * 32 + ak;
        float4 wv, bv;
        if (stat) {
            wv = __ldg(reinterpret_cast<const float4*>(lnw) + (kk >> 2));
            bv = __ldg(reinterpret_cast<const float4*>(lnb) + (kk >> 2));
        }
#pragma unroll
        for (int j = 0; j < 4; j++) {
            int r = bm + ar + 32 * j;
            float4 v = make_float4(0.f, 0.f, 0.f, 0.f);
            if (r < M)
                v = *reinterpret_cast<const float4*>(A + (size_t)r * DIM + kk);
            if (stat) {
                float2 s = __ldg(stat + min(r, M - 1));
                v.x = (v.x - s.x) * s.y * wv.x + bv.x;
                v.y = (v.y - s.x) * s.y * wv.y + bv.y;
                v.z = (v.z - s.x) * s.y * wv.z + bv.z;
                v.w = (v.w - s.x) * s.y * wv.w + bv.w;
            }
            uh[j][0] = pack_hi(v.x, v.y, ul[j][0]);
            uh[j][1] = pack_hi(v.z, v.w, ul[j][1]);
        }
    };
    auto storeA = [&](int s) {
        uint32_t* S = sm + s * SSTR;
#pragma unroll
        for (int j = 0; j < 4; j++) {
            uint32_t* d = S + (ar + 32 * j) * ASTR + ap;
            d[0]  = uh[j][0]; d[1]  = uh[j][1];
            d[16] = ul[j][0]; d[17] = ul[j][1];
        }
    };
    auto fillB = [&](int i, int s) {
        int kb = i * 16;
        uint32_t base = smb + (uint32_t)(s * SSTR + A_WORDS) * 4;
#pragma unroll
        for (int q = 0; q < 4; q++) {
            int c = t + 256 * q;
            int arr = c >> 9;
            int cc = c & 511;
            int row = cc >> 5, col16 = cc & 31;
            const uint32_t* src = (arr ? Wl : Wh) +
                (size_t)(kb + row) * 512 + bn + col16 * 4;
            uint32_t dst = base + (uint32_t)(((arr ? row + 16 : row) * BSTR +
                                              col16 * 4) * 4);
            cp16(dst, src);
        }
        asm volatile("cp.async.commit_group;" ::: "memory");
    };

    fillB(0, 0);
    loadRegs(0);
    storeA(0);
    asm volatile("cp.async.wait_group 0;" ::: "memory");
    __syncthreads();
    loadRegs(1);

    for (int i = 0; i < 16; i++) {
        const int cur = i & 1;
        if (i < 15) { storeA(cur ^ 1); fillB(i + 1, cur ^ 1); }
        if (i < 14) loadRegs(i + 2);

        const uint32_t* SA = sm + cur * SSTR;
        const uint32_t* SB = SA + A_WORDS;
#pragma unroll
        for (int ks = 0; ks < 2; ks++) {
            const int kkp = ks * 8;
            uint32_t bh[4][2], bl[4][2];
#pragma unroll
            for (int nf = 0; nf < 4; nf++) {
                int bi = (kkp + tig) * BSTR + n0 + nf * 8 + g;
                bh[nf][0] = SB[bi];
                bh[nf][1] = SB[bi + 4 * BSTR];
                bl[nf][0] = SB[bi + 16 * BSTR];
                bl[nf][1] = SB[bi + 20 * BSTR];
            }
#pragma unroll
            for (int mf = 0; mf < 4; mf++) {
                int am = (m0 + mf * 16 + g) * ASTR + kkp + tig;
                uint32_t ah[4], al[4];
                ah[0] = SA[am];            ah[1] = SA[am + 8 * ASTR];
                ah[2] = SA[am + 4];        ah[3] = SA[am + 8 * ASTR + 4];
                al[0] = SA[am + 16];       al[1] = SA[am + 8 * ASTR + 16];
                al[2] = SA[am + 20];       al[3] = SA[am + 8 * ASTR + 20];
#pragma unroll
                for (int nf = 0; nf < 4; nf++) {
                    mma_bf16(acc[mf][nf], ah, bh[nf]);
                    mma_bf16(acc[mf][nf], ah, bl[nf]);
                    mma_bf16(acc[mf][nf], al, bh[nf]);
                }
            }
        }
        if (i < 15) {
            asm volatile("cp.async.wait_group 0;" ::: "memory");
            __syncthreads();
        }
    }

#pragma unroll
    for (int mf = 0; mf < 4; mf++) {
        int row0 = bm + m0 + mf * 16 + g;
        float s0 = 0.f, ss0 = 0.f, s1 = 0.f, ss1 = 0.f;
#pragma unroll
        for (int nf = 0; nf < 4; nf++) {
            int col = bn + n0 + nf * 8 + tig * 2;
            float bv0 = __ldg(bias + col), bv1 = __ldg(bias + col + 1);
            float v0 = acc[mf][nf][0] + bv0, v1 = acc[mf][nf][1] + bv1;
            float v2 = acc[mf][nf][2] + bv0, v3 = acc[mf][nf][3] + bv1;
            if (relu) {
                v0 = fmaxf(v0, 0.f); v1 = fmaxf(v1, 0.f);
                v2 = fmaxf(v2, 0.f); v3 = fmaxf(v3, 0.f);
            }
            if (row0 < M)
                *reinterpret_cast<float2*>(C + (size_t)row0 * DIM + col) = make_float2(v0, v1);
            if (row0 + 8 < M)
                *reinterpret_cast<float2*>(C + (size_t)(row0 + 8) * DIM + col) = make_float2(v2, v3);
            if (emit) {
                s0 += v0 + v1; ss0 += v0 * v0 + v1 * v1;
                s1 += v2 + v3; ss1 += v2 * v2 + v3 * v3;
            }
        }
        if (emit) {
#pragma unroll
            for (int o = 1; o <= 2; o <<= 1) {
                s0  += __shfl_xor_sync(0xffffffffu, s0, o);
                ss0 += __shfl_xor_sync(0xffffffffu, ss0, o);
                s1  += __shfl_xor_sync(0xffffffffu, s1, o);
                ss1 += __shfl_xor_sync(0xffffffffu, ss1, o);
            }
            if (tig == 0) {
                if (row0 < M)
                    asm volatile("red.global.add.v2.f32 [%0], {%1, %2};"
                                 :: "l"(accv + row0), "f"(s0), "f"(ss0) : "memory");
                if (row0 + 8 < M)
                    asm volatile("red.global.add.v2.f32 [%0], {%1, %2};"
                                 :: "l"(accv + row0 + 8), "f"(s1), "f"(ss1) : "memory");
            }
        }
    }
}

// ---------------------------------------------------------------------------
// Final heads epilogue
// ---------------------------------------------------------------------------
__global__ void k_mix(const float* __restrict__ pre, const float* __restrict__ noise,
                      const float* __restrict__ mean, float* __restrict__ ostd,
                      float* __restrict__ ofin, size_t n)
{
    size_t i = (size_t)blockIdx.x * blockDim.x + threadIdx.x;
    size_t stride = (size_t)gridDim.x * blockDim.x;
    for (; i < n; i += stride) {
        float x = pre[i];
        float sp = fmaxf(x, 0.f) + log1pf(expf(-fabsf(x)));
        ostd[i] = sp;
        ofin[i] = fmaf(noise[i], sp, mean[i]);
    }
}

// ---------------------------------------------------------------------------
// Host orchestration
// ---------------------------------------------------------------------------
static uint32_t *d_wph, *d_wpl;
static float2 *d_stat, *d_acc;

static void run_gemm(const float* A, int slot, const float* bias, float* C,
                     int M, bool relu, bool ln, const float* lnw,
                     const float* lnb, bool emit) {
    dim3 grid(DIM / 128, (M + 127) / 128);
    k_gemm_tc<<<grid, 256, GEMM_SMEM>>>(
        A, d_wph + (size_t)slot * 256 * 512, d_wpl + (size_t)slot * 256 * 512,
        bias, C, M, relu ? 1 : 0, ln ? d_stat : nullptr, lnw, lnb,
        emit ? 1 : 0, d_acc);
}

struct MlpParams {
    const float *ln0w, *ln0b, *b1, *ln1w, *ln1b, *b2;
};

// AllSet MLP with fused LN + stat production. `in` stats must already be in
// d_stat. Output in `out` (never aliases `in`/`tmp`).
static void run_mlp(const float* in, float* tmp, float* out, const MlpParams& P,
                    int k, int N, bool emit_out) {
    run_gemm(in, k, P.b1 + (size_t)k * DIM, tmp, N, true, true,
             P.ln0w + (size_t)k * DIM, P.ln0b + (size_t)k * DIM, true);
    k_fin<<<(N + 255) / 256, 256>>>(d_acc, d_stat, N);
    run_gemm(tmp, 8 + k, P.b2 + (size_t)k * DIM, out, N, true, true,
             P.ln1w + (size_t)k * DIM, P.ln1b + (size_t)k * DIM, emit_out);
    if (emit_out) k_fin<<<(N + 255) / 256, 256>>>(d_acc, d_stat, N);
}

extern "C" void kernel_launch(void* const* d_in, const int* in_sizes, int n_in,
                              void* d_out, int out_size) {
    const float* x    = (const float*)d_in[0];
    const int*   eidx = (const int*)  d_in[1];
    const float* norm = (const float*)d_in[2];
    MlpParams P;
    P.ln0w = (const float*)d_in[3];
    P.ln0b = (const float*)d_in[4];
    const float* mlpW1 = (const float*)d_in[5];
    P.b1   = (const float*)d_in[6];
    P.ln1w = (const float*)d_in[7];
    P.ln1b = (const float*)d_in[8];
    const float* mlpW2 = (const float*)d_in[9];
    P.b2   = (const float*)d_in[10];
    const float* eW1    = (const float*)d_in[11];
    const float* eb1    = (const float*)d_in[12];
    const float* eW2    = (const float*)d_in[13];
    const float* eb2    = (const float*)d_in[14];
    const float* noiseN = (const float*)d_in[15];
    const float* noiseH = (const float*)d_in[16];
    float* out = (float*)d_out;

    const int* src = eidx;
    const int* dst = eidx + NE;

    float *n0, *n1, *n2, *h0, *h1, *h2;
    int *cntE, *cntV, *curE, *curV, *rpE, *rpV, *colE, *colV;
    cudaGetSymbolAddress((void**)&n0, g_n0);
    cudaGetSymbolAddress((void**)&n1, g_n1);
    cudaGetSymbolAddress((void**)&n2, g_n2);
    cudaGetSymbolAddress((void**)&h0, g_h0);
    cudaGetSymbolAddress((void**)&h1, g_h1);
    cudaGetSymbolAddress((void**)&h2, g_h2);
    cudaGetSymbolAddress((void**)&cntE, g_cntE);
    cudaGetSymbolAddress((void**)&cntV, g_cntV);
    cudaGetSymbolAddress((void**)&curE, g_curE);
    cudaGetSymbolAddress((void**)&curV, g_curV);
    cudaGetSymbolAddress((void**)&rpE, g_rpE);
    cudaGetSymbolAddress((void**)&rpV, g_rpV);
    cudaGetSymbolAddress((void**)&colE, g_colE);
    cudaGetSymbolAddress((void**)&colV, g_colV);
    cudaGetSymbolAddress((void**)&d_wph, g_wph);
    cudaGetSymbolAddress((void**)&d_wpl, g_wpl);
    cudaGetSymbolAddress((void**)&d_stat, g_stat);
    cudaGetSymbolAddress((void**)&d_acc, g_acc);

    cudaFuncSetAttribute(k_gemm_tc, cudaFuncAttributeMaxDynamicSharedMemorySize,
                         GEMM_SMEM);

    const size_t ND = (size_t)NN * DIM;
    const size_t HD = (size_t)NH * DIM;
    const size_t WSL = (size_t)256 * 512;

    // --- weight pre-split/pack ---
    {
        int tot8 = 8 * 256 * 512, tot4 = 4 * 256 * 512;
        k_wsplit<<<(tot8 + 255) / 256, 256>>>(mlpW1, d_wph, d_wpl, 8);
        k_wsplit<<<(tot8 + 255) / 256, 256>>>(mlpW2, d_wph + 8 * WSL, d_wpl + 8 * WSL, 8);
        k_wsplit<<<(tot4 + 255) / 256, 256>>>(eW1, d_wph + 16 * WSL, d_wpl + 16 * WSL, 4);
        k_wsplit<<<(tot4 + 255) / 256, 256>>>(eW2, d_wph + 20 * WSL, d_wpl + 20 * WSL, 4);
    }

    // --- CSR build ---
    k_init_min<<<1, 1>>>();
    k_min_reduce<<<256, 256>>>(dst, NE);
    k_zero4<<<32, 256>>>((float4*)cntE, NH / 4);
    k_zero4<<<64, 256>>>((float4*)cntV, NN / 4);
    k_zero4<<<32, 256>>>((float4*)curE, NH / 4);
    k_zero4<<<64, 256>>>((float4*)curV, NN / 4);
    k_cnt<<<(NE + 255) / 256, 256>>>(dst, cntE, NE, 1);
    k_cnt<<<(NE + 255) / 256, 256>>>(src, cntV, NE, 0);
    k_scan<<<1, 1024>>>(cntE, rpE, NH);
    k_scan<<<1, 1024>>>(cntV, rpV, NN);
    k_fill<<<(NE + 255) / 256, 256>>>(dst, rpE, curE, colE, NE, 1);
    k_fill<<<(NE + 255) / 256, 256>>>(src, rpV, curV, colV, NE, 0);

    // --- initial stats for x ---
    k_stat<<<(NN + 7) / 8, 256>>>(x, d_stat, NN);

    // --- layer 0 ---
    run_mlp(x, n0, n1, P, 0, NN, false);                          // V2E enc
    k_gather<<<NH, 128>>>(n1, h0, rpE, colE, src, norm, 0, d_stat);
    run_mlp(h0, h1, h2, P, 1, NH, true);                          // V2E dec -> x_he
    run_mlp(h2, h1, h0, P, 2, NH, false);                         // E2V enc
    k_gather<<<NN, 128>>>(h0, n0, rpV, colV, dst, norm, 1, d_stat);
    run_mlp(n0, n1, n2, P, 3, NN, true);                          // E2V dec -> x_node

    // --- layer 1 ---
    run_mlp(n2, n0, n1, P, 4, NN, false);
    k_gather<<<NH, 128>>>(n1, h0, rpE, colE, src, norm, 0, d_stat);
    run_mlp(h0, h1, h2, P, 5, NH, true);                          // x_he (kept)
    run_mlp(h2, h1, h0, P, 6, NH, false);
    k_gather<<<NN, 128>>>(h0, n0, rpV, colV, dst, norm, 1, d_stat);
    run_mlp(n0, n1, n2, P, 7, NN, false);                         // x_node (kept)

    // --- heads ---
    float* oFinN  = out;
    float* oMeanN = out + ND;
    float* oStdN  = out + 2 * ND;
    float* oFinH  = out + 3 * ND;
    float* oMeanH = out + 3 * ND + HD;
    float* oStdH  = out + 3 * ND + 2 * HD;

    run_gemm(n2, 16, eb1 + 0 * DIM, n0, NN, true, false, nullptr, nullptr, false);
    run_gemm(n0, 20, eb2 + 0 * DIM, oMeanN, NN, false, false, nullptr, nullptr, false);
    run_gemm(n2, 17, eb1 + 1 * DIM, n0, NN, true, false, nullptr, nullptr, false);
    run_gemm(n0, 21, eb2 + 1 * DIM, n1, NN, false, false, nullptr, nullptr, false);
    k_mix<<<8192, 256>>>(n1, noiseN, oMeanN, oStdN, oFinN, ND);

    run_gemm(h2, 18, eb1 + 2 * DIM, h0, NH, true, false, nullptr, nullptr, false);
    run_gemm(h0, 22, eb2 + 2 * DIM, oMeanH, NH, false, false, nullptr, nullptr, false);
    run_gemm(h2, 19, eb1 + 3 * DIM, h0, NH, true, false, nullptr, nullptr, false);
    run_gemm(h0, 23, eb2 + 3 * DIM, h1, NH, false, false, nullptr, nullptr, false);
    k_mix<<<4096, 256>>>(h1, noiseH, oMeanH, oStdH, oFinH, HD);

    (void)in_sizes; (void)n_in; (void)out_size;
}

// round 15
// speedup vs baseline: 1.1098x; 1.1098x over previous
#include <cuda_runtime.h>
#include <cuda_bf16.h>
#include <math.h>
#include <stdint.h>

#define NN 50000
#define NH 10000
#define NE 250000
#define DIM 512
#define NSLOT 24

// ---------------------------------------------------------------------------
// Static scratch (no allocation allowed)
// ---------------------------------------------------------------------------
__device__ float g_n0[(size_t)NN * DIM];
__device__ float g_n1[(size_t)NN * DIM];
__device__ float g_n2[(size_t)NN * DIM];
__device__ float g_h0[(size_t)NH * DIM];
__device__ float g_h1[(size_t)NH * DIM];
__device__ float g_h2[(size_t)NH * DIM];
__device__ float2 g_stat[NN];
__device__ int   g_minv;
// packed split weights: [slot][kpair][n], word = bf16(k even)|bf16(k odd)<<16
__device__ uint32_t g_wph[(size_t)NSLOT * 256 * 512];
__device__ uint32_t g_wpl[(size_t)NSLOT * 256 * 512];
// CSR structures (rebuilt every call)
__device__ int g_cntE[NH], g_cntV[NN];
__device__ int g_curE[NH], g_curV[NN];
__device__ int g_rpE[NH + 1], g_rpV[NN + 1];
__device__ int g_colE[NE], g_colV[NE];

// ---------------------------------------------------------------------------
// Graph preprocessing
// ---------------------------------------------------------------------------
__global__ void k_init_min() { g_minv = 0x7fffffff; }

__global__ void k_min_reduce(const int* __restrict__ idx, int n) {
    int v = 0x7fffffff;
    for (int i = blockIdx.x * blockDim.x + threadIdx.x; i < n;
         i += gridDim.x * blockDim.x)
        v = min(v, __ldg(idx + i));
#pragma unroll
    for (int o = 16; o > 0; o >>= 1) v = min(v, __shfl_xor_sync(0xffffffffu, v, o));
    if ((threadIdx.x & 31) == 0) atomicMin(&g_minv, v);
}

__global__ void k_zero4(float4* __restrict__ p, size_t n4) {
    size_t i = (size_t)blockIdx.x * blockDim.x + threadIdx.x;
    size_t stride = (size_t)gridDim.x * blockDim.x;
    float4 z = make_float4(0.f, 0.f, 0.f, 0.f);
    for (; i < n4; i += stride) p[i] = z;
}

__global__ void k_cnt(const int* __restrict__ idx, int* __restrict__ cnt,
                      int n, int shift) {
    int i = blockIdx.x * blockDim.x + threadIdx.x;
    if (i < n) atomicAdd(&cnt[__ldg(idx + i) - (shift ? g_minv : 0)], 1);
}

__global__ __launch_bounds__(1024) void k_scan(const int* __restrict__ cnt,
                                               int* __restrict__ rp, int n) {
    __shared__ int part[1024];
    int t = threadIdx.x;
    int C = (n + 1023) >> 10;
    int base = t * C;
    int sum = 0;
    for (int i = 0; i < C; i++)
        if (base + i < n) sum += cnt[base + i];
    part[t] = sum;
    __syncthreads();
    for (int o = 1; o < 1024; o <<= 1) {
        int v = (t >= o) ? part[t - o] : 0;
        __syncthreads();
        part[t] += v;
        __syncthreads();
    }
    int excl = (t == 0) ? 0 : part[t - 1];
    for (int i = 0; i < C; i++)
        if (base + i < n) { rp[base + i] = excl; excl += cnt[base + i]; }
    if (t == 1023) rp[n] = part[1023];
}

__global__ void k_fill(const int* __restrict__ idx, const int* __restrict__ rp,
                       int* __restrict__ cur, int* __restrict__ col,
                       int n, int shift) {
    int i = blockIdx.x * blockDim.x + threadIdx.x;
    if (i < n) {
        int s = __ldg(idx + i) - (shift ? g_minv : 0);
        int p = atomicAdd(&cur[s], 1);
        col[rp[s] + p] = i;
    }
}

// ---------------------------------------------------------------------------
// Weight pre-split + pack
// ---------------------------------------------------------------------------
__global__ void k_wsplit(const float* __restrict__ W, uint32_t* __restrict__ oh,
                         uint32_t* __restrict__ ol, int nmat) {
    int i = blockIdx.x * blockDim.x + threadIdx.x;
    int total = nmat * 256 * 512;
    if (i >= total) return;
    int mat = i >> 17;
    int rem = i & 131071;
    int kp = rem >> 9, n = rem & 511;
    const float* src = W + (size_t)mat * DIM * DIM;
    float a = __ldg(src + (size_t)(2 * kp) * DIM + n);
    float b = __ldg(src + (size_t)(2 * kp + 1) * DIM + n);
    __nv_bfloat16 ha = __float2bfloat16(a), hb = __float2bfloat16(b);
    oh[i] = (uint32_t)__bfloat16_as_ushort(ha) |
            ((uint32_t)__bfloat16_as_ushort(hb) << 16);
    ol[i] = (uint32_t)__bfloat16_as_ushort(__float2bfloat16(a - __bfloat162float(ha))) |
            ((uint32_t)__bfloat16_as_ushort(__float2bfloat16(b - __bfloat162float(hb))) << 16);
}

// ---------------------------------------------------------------------------
// LN row statistics
// ---------------------------------------------------------------------------
__global__ __launch_bounds__(256) void k_stat(const float* __restrict__ in,
                                              float2* __restrict__ st, int N) {
    int warp = threadIdx.x >> 5, lane = threadIdx.x & 31;
    int row = blockIdx.x * 8 + warp;
    if (row >= N) return;
    const float4* ip = reinterpret_cast<const float4*>(in + (size_t)row * DIM);
    float s = 0.f, ss = 0.f;
#pragma unroll
    for (int j = 0; j < 4; j++) {
        float4 v = ip[lane + 32 * j];
        s  += v.x + v.y + v.z + v.w;
        ss += v.x * v.x + v.y * v.y + v.z * v.z + v.w * v.w;
    }
#pragma unroll
    for (int o = 16; o > 0; o >>= 1) {
        s  += __shfl_xor_sync(0xffffffffu, s, o);
        ss += __shfl_xor_sync(0xffffffffu, ss, o);
    }
    if (lane == 0) {
        float mu = s * (1.f / DIM);
        st[row] = make_float2(mu, rsqrtf(ss * (1.f / DIM) - mu * mu + 1e-5f));
    }
}

// ---------------------------------------------------------------------------
// CSR segment-mean gather; also emits LN stats of its output rows
// ---------------------------------------------------------------------------
__global__ __launch_bounds__(128) void k_gather(
    const float* __restrict__ feat, float* __restrict__ out,
    const int* __restrict__ rp, const int* __restrict__ col,
    const int* __restrict__ gidx, const float* __restrict__ norm, int gshift,
    float2* __restrict__ st)
{
    int seg = blockIdx.x;
    int beg = rp[seg], end = rp[seg + 1];
    int t = threadIdx.x;
    int mv = g_minv;
    __shared__ int   se[128];
    __shared__ float sn[128];
    __shared__ float rs[4], rss[4];
    float4 acc = make_float4(0.f, 0.f, 0.f, 0.f);
    for (int base = beg; base < end; base += 128) {
        int nb = min(128, end - base);
        if (t < nb) {
            int e = __ldg(col + base + t);
            se[t] = __ldg(gidx + e) - (gshift ? mv : 0);
            sn[t] = __ldg(norm + e);
        }
        __syncthreads();
        for (int j = 0; j < nb; j++) {
            float4 v = *reinterpret_cast<const float4*>(
                feat + (size_t)se[j] * DIM + t * 4);
            float nv = sn[j];
            acc.x = fmaf(nv, v.x, acc.x);
            acc.y = fmaf(nv, v.y, acc.y);
            acc.z = fmaf(nv, v.z, acc.z);
            acc.w = fmaf(nv, v.w, acc.w);
        }
        __syncthreads();
    }
    float inv = 1.f / fmaxf((float)(end - beg), 1.f);
    acc.x *= inv; acc.y *= inv; acc.z *= inv; acc.w *= inv;
    *reinterpret_cast<float4*>(out + (size_t)seg * DIM + t * 4) = acc;

    float s  = acc.x + acc.y + acc.z + acc.w;
    float ss = acc.x * acc.x + acc.y * acc.y + acc.z * acc.z + acc.w * acc.w;
#pragma unroll
    for (int o = 16; o > 0; o >>= 1) {
        s  += __shfl_xor_sync(0xffffffffu, s, o);
        ss += __shfl_xor_sync(0xffffffffu, ss, o);
    }
    int wid = t >> 5;
    if ((t & 31) == 0) { rs[wid] = s; rss[wid] = ss; }
    __syncthreads();
    if (t == 0) {
        s  = rs[0] + rs[1] + rs[2] + rs[3];
        ss = rss[0] + rss[1] + rss[2] + rss[3];
        float mu = s * (1.f / DIM);
        st[seg] = make_float2(mu, rsqrtf(ss * (1.f / DIM) - mu * mu + 1e-5f));
    }
}

// ---------------------------------------------------------------------------
// Split-bf16 GEMM, BM-templated (128 for NN, 64 for NH), double-buffered,
// packed-W via cp.async, fused LN on A.
// ---------------------------------------------------------------------------
#define ASTR 36
#define BSTR 136

__device__ __forceinline__ uint32_t pack_hi(float a, float b, uint32_t& lo) {
    __nv_bfloat16 ha = __float2bfloat16(a), hb = __float2bfloat16(b);
    lo = (uint32_t)__bfloat16_as_ushort(__float2bfloat16(a - __bfloat162float(ha))) |
         ((uint32_t)__bfloat16_as_ushort(__float2bfloat16(b - __bfloat162float(hb))) << 16);
    return (uint32_t)__bfloat16_as_ushort(ha) |
           ((uint32_t)__bfloat16_as_ushort(hb) << 16);
}

__device__ __forceinline__ void mma_bf16(float* c, const uint32_t* a,
                                         const uint32_t* b) {
    asm volatile(
        "mma.sync.aligned.m16n8k16.row.col.f32.bf16.bf16.f32 "
        "{%0,%1,%2,%3}, {%4,%5,%6,%7}, {%8,%9}, {%0,%1,%2,%3};"
        : "+f"(c[0]), "+f"(c[1]), "+f"(c[2]), "+f"(c[3])
        : "r"(a[0]), "r"(a[1]), "r"(a[2]), "r"(a[3]), "r"(b[0]), "r"(b[1]));
}

__device__ __forceinline__ void cp16(uint32_t d, const void* s) {
    asm volatile("cp.async.cg.shared.global [%0], [%1], 16;"
                 :: "r"(d), "l"(s) : "memory");
}

__device__ __forceinline__ uint32_t s2u(const void* p) {
    uint32_t r;
    asm("{ .reg .u64 t; cvta.to.shared.u64 t, %1; cvt.u32.u64 %0, t; }"
        : "=r"(r) : "l"(p));
    return r;
}

template <int BM>
__global__ __launch_bounds__(256, 2) void k_gemm_tc(
    const float* __restrict__ A,
    const uint32_t* __restrict__ Wh, const uint32_t* __restrict__ Wl,
    const float* __restrict__ bias, float* __restrict__ C, int M, int relu,
    const float2* __restrict__ stat, const float* __restrict__ lnw,
    const float* __restrict__ lnb)
{
    constexpr int MF = BM / 32;           // m-fragments per warp (x16 rows)
    constexpr int AW = BM * ASTR;         // A words per stage
    constexpr int SS = AW + 32 * BSTR;    // stage words
    extern __shared__ uint32_t sm[];
    const uint32_t smb = s2u(sm);

    const int t    = threadIdx.x;
    const int bm   = blockIdx.y * BM;
    const int bn   = blockIdx.x * 128;
    const int w    = t >> 5;
    const int lane = t & 31;
    const int g    = lane >> 2;
    const int tig  = lane & 3;
    const int m0   = (w & 1) * (BM / 2);
    const int n0   = (w >> 1) * 32;

    const int ar = t >> 3;          // 0..31
    const int ak = (t & 7) << 2;
    const int ap = (t & 7) << 1;

    float acc[MF][4][4];
#pragma unroll
    for (int mf = 0; mf < MF; mf++)
#pragma unroll
        for (int nf = 0; nf < 4; nf++)
#pragma unroll
            for (int i = 0; i < 4; i++) acc[mf][nf][i] = 0.f;

    uint32_t uh[BM / 32][2], ul[BM / 32][2];

    auto loadRegs = [&](int i) {
        int kk = i * 32 + ak;
        float4 wv, bv;
        if (stat) {
            wv = __ldg(reinterpret_cast<const float4*>(lnw) + (kk >> 2));
            bv = __ldg(reinterpret_cast<const float4*>(lnb) + (kk >> 2));
        }
#pragma unroll
        for (int j = 0; j < BM / 32; j++) {
            int r = bm + ar + 32 * j;
            float4 v = make_float4(0.f, 0.f, 0.f, 0.f);
            if (r < M)
                v = *reinterpret_cast<const float4*>(A + (size_t)r * DIM + kk);
            if (stat) {
                float2 s = __ldg(stat + min(r, M - 1));
                v.x = (v.x - s.x) * s.y * wv.x + bv.x;
                v.y = (v.y - s.x) * s.y * wv.y + bv.y;
                v.z = (v.z - s.x) * s.y * wv.z + bv.z;
                v.w = (v.w - s.x) * s.y * wv.w + bv.w;
            }
            uh[j][0] = pack_hi(v.x, v.y, ul[j][0]);
            uh[j][1] = pack_hi(v.z, v.w, ul[j][1]);
        }
    };
    auto storeA = [&](int s) {
        uint32_t* S = sm + s * SS;
#pragma unroll
        for (int j = 0; j < BM / 32; j++) {
            uint32_t* d = S + (ar + 32 * j) * ASTR + ap;
            d[0]  = uh[j][0]; d[1]  = uh[j][1];
            d[16] = ul[j][0]; d[17] = ul[j][1];
        }
    };
    auto fillB = [&](int i, int s) {
        int kb = i * 16;
        uint32_t base = smb + (uint32_t)(s * SS + AW) * 4;
#pragma unroll
        for (int q = 0; q < 4; q++) {
            int c = t + 256 * q;
            int arr = c >> 9;
            int cc = c & 511;
            int row = cc >> 5, col16 = cc & 31;
            const uint32_t* src = (arr ? Wl : Wh) +
                (size_t)(kb + row) * 512 + bn + col16 * 4;
            uint32_t dst = base + (uint32_t)(((arr ? row + 16 : row) * BSTR +
                                              col16 * 4) * 4);
            cp16(dst, src);
        }
        asm volatile("cp.async.commit_group;" ::: "memory");
    };

    fillB(0, 0);
    loadRegs(0);
    storeA(0);
    asm volatile("cp.async.wait_group 0;" ::: "memory");
    __syncthreads();
    loadRegs(1);

    for (int i = 0; i < 16; i++) {
        const int cur = i & 1;
        if (i < 15) { storeA(cur ^ 1); fillB(i + 1, cur ^ 1); }
        if (i < 14) loadRegs(i + 2);

        const uint32_t* SA = sm + cur * SS;
        const uint32_t* SB = SA + AW;
#pragma unroll
        for (int ks = 0; ks < 2; ks++) {
            const int kkp = ks * 8;
            uint32_t bh[4][2], bl[4][2];
#pragma unroll
            for (int nf = 0; nf < 4; nf++) {
                int bi = (kkp + tig) * BSTR + n0 + nf * 8 + g;
                bh[nf][0] = SB[bi];
                bh[nf][1] = SB[bi + 4 * BSTR];
                bl[nf][0] = SB[bi + 16 * BSTR];
                bl[nf][1] = SB[bi + 20 * BSTR];
            }
#pragma unroll
            for (int mf = 0; mf < MF; mf++) {
                int am = (m0 + mf * 16 + g) * ASTR + kkp + tig;
                uint32_t ah[4], al[4];
                ah[0] = SA[am];            ah[1] = SA[am + 8 * ASTR];
                ah[2] = SA[am + 4];        ah[3] = SA[am + 8 * ASTR + 4];
                al[0] = SA[am + 16];       al[1] = SA[am + 8 * ASTR + 16];
                al[2] = SA[am + 20];       al[3] = SA[am + 8 * ASTR + 20];
#pragma unroll
                for (int nf = 0; nf < 4; nf++) {
                    mma_bf16(acc[mf][nf], ah, bh[nf]);
                    mma_bf16(acc[mf][nf], ah, bl[nf]);
                    mma_bf16(acc[mf][nf], al, bh[nf]);
                }
            }
        }
        if (i < 15) {
            asm volatile("cp.async.wait_group 0;" ::: "memory");
            __syncthreads();
        }
    }

#pragma unroll
    for (int mf = 0; mf < MF; mf++) {
        int row0 = bm + m0 + mf * 16 + g;
#pragma unroll
        for (int nf = 0; nf < 4; nf++) {
            int col = bn + n0 + nf * 8 + tig * 2;
            float bv0 = __ldg(bias + col), bv1 = __ldg(bias + col + 1);
            float v0 = acc[mf][nf][0] + bv0, v1 = acc[mf][nf][1] + bv1;
            float v2 = acc[mf][nf][2] + bv0, v3 = acc[mf][nf][3] + bv1;
            if (relu) {
                v0 = fmaxf(v0, 0.f); v1 = fmaxf(v1, 0.f);
                v2 = fmaxf(v2, 0.f); v3 = fmaxf(v3, 0.f);
            }
            if (row0 < M)
                *reinterpret_cast<float2*>(C + (size_t)row0 * DIM + col) = make_float2(v0, v1);
            if (row0 + 8 < M)
                *reinterpret_cast<float2*>(C + (size_t)(row0 + 8) * DIM + col) = make_float2(v2, v3);
        }
    }
}

#define SMEM128 (2 * (128 * ASTR + 32 * BSTR) * 4)
#define SMEM64  (2 * (64  * ASTR + 32 * BSTR) * 4)

// ---------------------------------------------------------------------------
// Final heads epilogue
// ---------------------------------------------------------------------------
__global__ void k_mix(const float* __restrict__ pre, const float* __restrict__ noise,
                      const float* __restrict__ mean, float* __restrict__ ostd,
                      float* __restrict__ ofin, size_t n)
{
    size_t i = (size_t)blockIdx.x * blockDim.x + threadIdx.x;
    size_t stride = (size_t)gridDim.x * blockDim.x;
    for (; i < n; i += stride) {
        float x = pre[i];
        float sp = fmaxf(x, 0.f) + log1pf(expf(-fabsf(x)));
        ostd[i] = sp;
        ofin[i] = fmaf(noise[i], sp, mean[i]);
    }
}

// ---------------------------------------------------------------------------
// Host orchestration
// ---------------------------------------------------------------------------
static uint32_t *d_wph, *d_wpl;
static float2 *d_stat;

static void run_gemm(const float* A, int slot, const float* bias, float* C,
                     int M, bool relu, bool ln, const float* lnw,
                     const float* lnb) {
    const uint32_t* Wh = d_wph + (size_t)slot * 256 * 512;
    const uint32_t* Wl = d_wpl + (size_t)slot * 256 * 512;
    if (M > 16384) {
        dim3 grid(4, (M + 127) / 128);
        k_gemm_tc<128><<<grid, 256, SMEM128>>>(A, Wh, Wl, bias, C, M,
                                               relu ? 1 : 0,
                                               ln ? d_stat : nullptr, lnw, lnb);
    } else {
        dim3 grid(4, (M + 63) / 64);
        k_gemm_tc<64><<<grid, 256, SMEM64>>>(A, Wh, Wl, bias, C, M,
                                             relu ? 1 : 0,
                                             ln ? d_stat : nullptr, lnw, lnb);
    }
}

struct MlpParams {
    const float *ln0w, *ln0b, *b1, *ln1w, *ln1b, *b2;
};

// MLP: input stats must already be in d_stat
static void run_mlp(const float* in, float* tmp, float* out, const MlpParams& P,
                    int k, int N) {
    run_gemm(in, k, P.b1 + (size_t)k * DIM, tmp, N, true, true,
             P.ln0w + (size_t)k * DIM, P.ln0b + (size_t)k * DIM);
    k_stat<<<(N + 7) / 8, 256>>>(tmp, d_stat, N);
    run_gemm(tmp, 8 + k, P.b2 + (size_t)k * DIM, out, N, true, true,
             P.ln1w + (size_t)k * DIM, P.ln1b + (size_t)k * DIM);
}

extern "C" void kernel_launch(void* const* d_in, const int* in_sizes, int n_in,
                              void* d_out, int out_size) {
    const float* x    = (const float*)d_in[0];
    const int*   eidx = (const int*)  d_in[1];
    const float* norm = (const float*)d_in[2];
    MlpParams P;
    P.ln0w = (const float*)d_in[3];
    P.ln0b = (const float*)d_in[4];
    const float* mlpW1 = (const float*)d_in[5];
    P.b1   = (const float*)d_in[6];
    P.ln1w = (const float*)d_in[7];
    P.ln1b = (const float*)d_in[8];
    const float* mlpW2 = (const float*)d_in[9];
    P.b2   = (const float*)d_in[10];
    const float* eW1    = (const float*)d_in[11];
    const float* eb1    = (const float*)d_in[12];
    const float* eW2    = (const float*)d_in[13];
    const float* eb2    = (const float*)d_in[14];
    const float* noiseN = (const float*)d_in[15];
    const float* noiseH = (const float*)d_in[16];
    float* out = (float*)d_out;

    const int* src = eidx;
    const int* dst = eidx + NE;

    float *n0, *n1, *n2, *h0, *h1, *h2;
    int *cntE, *cntV, *curE, *curV, *rpE, *rpV, *colE, *colV;
    cudaGetSymbolAddress((void**)&n0, g_n0);
    cudaGetSymbolAddress((void**)&n1, g_n1);
    cudaGetSymbolAddress((void**)&n2, g_n2);
    cudaGetSymbolAddress((void**)&h0, g_h0);
    cudaGetSymbolAddress((void**)&h1, g_h1);
    cudaGetSymbolAddress((void**)&h2, g_h2);
    cudaGetSymbolAddress((void**)&cntE, g_cntE);
    cudaGetSymbolAddress((void**)&cntV, g_cntV);
    cudaGetSymbolAddress((void**)&curE, g_curE);
    cudaGetSymbolAddress((void**)&curV, g_curV);
    cudaGetSymbolAddress((void**)&rpE, g_rpE);
    cudaGetSymbolAddress((void**)&rpV, g_rpV);
    cudaGetSymbolAddress((void**)&colE, g_colE);
    cudaGetSymbolAddress((void**)&colV, g_colV);
    cudaGetSymbolAddress((void**)&d_wph, g_wph);
    cudaGetSymbolAddress((void**)&d_wpl, g_wpl);
    cudaGetSymbolAddress((void**)&d_stat, g_stat);

    cudaFuncSetAttribute(k_gemm_tc<128>,
                         cudaFuncAttributeMaxDynamicSharedMemorySize, SMEM128);
    cudaFuncSetAttribute(k_gemm_tc<64>,
                         cudaFuncAttributeMaxDynamicSharedMemorySize, SMEM64);

    const size_t ND = (size_t)NN * DIM;
    const size_t HD = (size_t)NH * DIM;
    const size_t WSL = (size_t)256 * 512;

    // --- weight pre-split/pack ---
    {
        int tot8 = 8 * 256 * 512, tot4 = 4 * 256 * 512;
        k_wsplit<<<(tot8 + 255) / 256, 256>>>(mlpW1, d_wph, d_wpl, 8);
        k_wsplit<<<(tot8 + 255) / 256, 256>>>(mlpW2, d_wph + 8 * WSL, d_wpl + 8 * WSL, 8);
        k_wsplit<<<(tot4 + 255) / 256, 256>>>(eW1, d_wph + 16 * WSL, d_wpl + 16 * WSL, 4);
        k_wsplit<<<(tot4 + 255) / 256, 256>>>(eW2, d_wph + 20 * WSL, d_wpl + 20 * WSL, 4);
    }

    // --- CSR build ---
    k_init_min<<<1, 1>>>();
    k_min_reduce<<<256, 256>>>(dst, NE);
    k_zero4<<<32, 256>>>((float4*)cntE, NH / 4);
    k_zero4<<<64, 256>>>((float4*)cntV, NN / 4);
    k_zero4<<<32, 256>>>((float4*)curE, NH / 4);
    k_zero4<<<64, 256>>>((float4*)curV, NN / 4);
    k_cnt<<<(NE + 255) / 256, 256>>>(dst, cntE, NE, 1);
    k_cnt<<<(NE + 255) / 256, 256>>>(src, cntV, NE, 0);
    k_scan<<<1, 1024>>>(cntE, rpE, NH);
    k_scan<<<1, 1024>>>(cntV, rpV, NN);
    k_fill<<<(NE + 255) / 256, 256>>>(dst, rpE, curE, colE, NE, 1);
    k_fill<<<(NE + 255) / 256, 256>>>(src, rpV, curV, colV, NE, 0);

    // --- layer 0 ---
    k_stat<<<(NN + 7) / 8, 256>>>(x, d_stat, NN);
    run_mlp(x, n0, n1, P, 0, NN);                                 // V2E enc
    k_gather<<<NH, 128>>>(n1, h0, rpE, colE, src, norm, 0, d_stat);
    run_mlp(h0, h1, h2, P, 1, NH);                                // x_he
    k_stat<<<(NH + 7) / 8, 256>>>(h2, d_stat, NH);
    run_mlp(h2, h1, h0, P, 2, NH);                                // E2V enc
    k_gather<<<NN, 128>>>(h0, n0, rpV, colV, dst, norm, 1, d_stat);
    run_mlp(n0, n1, n2, P, 3, NN);                                // x_node

    // --- layer 1 ---
    k_stat<<<(NN + 7) / 8, 256>>>(n2, d_stat, NN);
    run_mlp(n2, n0, n1, P, 4, NN);
    k_gather<<<NH, 128>>>(n1, h0, rpE, colE, src, norm, 0, d_stat);
    run_mlp(h0, h1, h2, P, 5, NH);                                // x_he final
    k_stat<<<(NH + 7) / 8, 256>>>(h2, d_stat, NH);
    run_mlp(h2, h1, h0, P, 6, NH);                                // E2V enc
    k_gather<<<NN, 128>>>(h0, n0, rpV, colV, dst, norm, 1, d_stat);
    run_mlp(n0, n1, n2, P, 7, NN);                                // x_node final

    // --- heads ---
    float* oFinN  = out;
    float* oMeanN = out + ND;
    float* oStdN  = out + 2 * ND;
    float* oFinH  = out + 3 * ND;
    float* oMeanH = out + 3 * ND + HD;
    float* oStdH  = out + 3 * ND + 2 * HD;

    run_gemm(n2, 16, eb1 + 0 * DIM, n0, NN, true, false, nullptr, nullptr);
    run_gemm(n0, 20, eb2 + 0 * DIM, oMeanN, NN, false, false, nullptr, nullptr);
    run_gemm(n2, 17, eb1 + 1 * DIM, n0, NN, true, false, nullptr, nullptr);
    run_gemm(n0, 21, eb2 + 1 * DIM, n1, NN, false, false, nullptr, nullptr);
    k_mix<<<8192, 256>>>(n1, noiseN, oMeanN, oStdN, oFinN, ND);

    run_gemm(h2, 18, eb1 + 2 * DIM, h0, NH, true, false, nullptr, nullptr);
    run_gemm(h0, 22, eb2 + 2 * DIM, oMeanH, NH, false, false, nullptr, nullptr);
    run_gemm(h2, 19, eb1 + 3 * DIM, h0, NH, true, false, nullptr, nullptr);
    run_gemm(h0, 23, eb2 + 3 * DIM, h1, NH, false, false, nullptr, nullptr);
    k_mix<<<4096, 256>>>(h1, noiseH, oMeanH, oStdH, oFinH, HD);

    (void)in_sizes; (void)n_in; (void)out_size;
}